// round 1
// baseline (speedup 1.0000x reference)
#include <cuda_runtime.h>
#include <math.h>

#define HID   1024
#define BATCH 4096
#define KPS   256
#define G4H   (4 * HID)

// Scratch: gates for 3 LSTMs + embedded input frame.
// __device__ globals are the sanctioned no-alloc scratch mechanism.
__device__ float g_inframe[(size_t)BATCH * KPS];
__device__ float g_gates[3][(size_t)BATCH * G4H];

// ---------------------------------------------------------------------------
// Dual-input SGEMM with bias:  C[M,N] = A1@W1^T + A2@W2^T + bias1 + bias2
//   A: [M,K] row-major, W: [N,K] row-major (both K-contiguous -> "NT" gemm)
// Tile: BM=128, BN=128, BK=16, 256 threads, 8x8 per-thread accumulator.
// All dims assumed multiples of tile sizes (true here: M=4096, N in {256,4096},
// K in {256,1024}).
// ---------------------------------------------------------------------------
template <int BM, int BN, int BK, int TM, int TN>
__global__ void __launch_bounds__(256)
gemm_dual_bias(const float* __restrict__ A1, const float* __restrict__ W1, int K1,
               const float* __restrict__ A2, const float* __restrict__ W2, int K2,
               const float* __restrict__ bias1, const float* __restrict__ bias2,
               float* __restrict__ C, int N)
{
    __shared__ float As[BK][BM];
    __shared__ float Bs[BK][BN];

    const int tid = threadIdx.x;
    const int m0  = blockIdx.y * BM;
    const int n0  = blockIdx.x * BN;

    // 16x16 thread grid; each thread owns an 8x8 sub-tile
    const int ty = tid >> 4;   // 0..15
    const int tx = tid & 15;   // 0..15

    float acc[TM][TN];
#pragma unroll
    for (int i = 0; i < TM; i++)
#pragma unroll
        for (int j = 0; j < TN; j++) acc[i][j] = 0.0f;

#pragma unroll 1
    for (int pass = 0; pass < 2; pass++) {
        const float* A = pass ? A2 : A1;
        const float* W = pass ? W2 : W1;
        const int    K = pass ? K2 : K1;
        if (A == nullptr) continue;

        for (int k0 = 0; k0 < K; k0 += BK) {
            // Load A tile: BM x BK = 128*16 floats = 512 float4, 2 per thread.
#pragma unroll
            for (int l = 0; l < (BM * BK) / (256 * 4); l++) {
                int f    = tid + l * 256;          // float4 index
                int row  = f / (BK / 4);           // 0..127
                int col4 = (f % (BK / 4)) * 4;     // 0,4,8,12
                float4 v = *(const float4*)(A + (size_t)(m0 + row) * K + k0 + col4);
                As[col4 + 0][row] = v.x;
                As[col4 + 1][row] = v.y;
                As[col4 + 2][row] = v.z;
                As[col4 + 3][row] = v.w;
            }
            // Load W tile: BN x BK, same pattern.
#pragma unroll
            for (int l = 0; l < (BN * BK) / (256 * 4); l++) {
                int f    = tid + l * 256;
                int row  = f / (BK / 4);
                int col4 = (f % (BK / 4)) * 4;
                float4 v = *(const float4*)(W + (size_t)(n0 + row) * K + k0 + col4);
                Bs[col4 + 0][row] = v.x;
                Bs[col4 + 1][row] = v.y;
                Bs[col4 + 2][row] = v.z;
                Bs[col4 + 3][row] = v.w;
            }
            __syncthreads();

#pragma unroll
            for (int k = 0; k < BK; k++) {
                float4 a0 = *(const float4*)&As[k][ty * TM];
                float4 a1 = *(const float4*)&As[k][ty * TM + 4];
                float4 b0 = *(const float4*)&Bs[k][tx * TN];
                float4 b1 = *(const float4*)&Bs[k][tx * TN + 4];
                float ar[TM] = {a0.x, a0.y, a0.z, a0.w, a1.x, a1.y, a1.z, a1.w};
                float br[TN] = {b0.x, b0.y, b0.z, b0.w, b1.x, b1.y, b1.z, b1.w};
#pragma unroll
                for (int i = 0; i < TM; i++)
#pragma unroll
                    for (int j = 0; j < TN; j++)
                        acc[i][j] = fmaf(ar[i], br[j], acc[i][j]);
            }
            __syncthreads();
        }
    }

    // Epilogue: add bias, store (each thread's 8 columns are contiguous).
#pragma unroll
    for (int i = 0; i < TM; i++) {
        int m = m0 + ty * TM + i;
        int n = n0 + tx * TN;
        float bsum[TN];
#pragma unroll
        for (int j = 0; j < TN; j++) {
            bsum[j] = bias1 ? bias1[n + j] : 0.0f;
            if (bias2) bsum[j] += bias2[n + j];
        }
        float4 o0 = make_float4(acc[i][0] + bsum[0], acc[i][1] + bsum[1],
                                acc[i][2] + bsum[2], acc[i][3] + bsum[3]);
        float4 o1 = make_float4(acc[i][4] + bsum[4], acc[i][5] + bsum[5],
                                acc[i][6] + bsum[6], acc[i][7] + bsum[7]);
        *(float4*)(C + (size_t)m * N + n)     = o0;
        *(float4*)(C + (size_t)m * N + n + 4) = o1;
    }
}

// ---------------------------------------------------------------------------
// Pointwise LSTM activation: gates [B,4H] (i,f,g,o) + c_old -> h_new, c_new
// ---------------------------------------------------------------------------
__device__ __forceinline__ float sigmoidf(float x) {
    return 1.0f / (1.0f + __expf(-x));
}

__global__ void lstm_pointwise(const float* __restrict__ gates,
                               const float* __restrict__ c_old,
                               float* __restrict__ h_out,
                               float* __restrict__ h_out2,   // optional duplicate
                               float* __restrict__ c_out)
{
    int idx = blockIdx.x * blockDim.x + threadIdx.x;
    if (idx >= BATCH * HID) return;
    int b = idx >> 10;          // /HID
    int j = idx & (HID - 1);    // %HID
    const float* gr = gates + (size_t)b * G4H;
    float ig = sigmoidf(gr[j]);
    float fg = sigmoidf(gr[HID + j]);
    float gg = tanhf(gr[2 * HID + j]);
    float og = sigmoidf(gr[3 * HID + j]);
    float cn = fg * c_old[idx] + ig * gg;
    float hn = og * tanhf(cn);
    c_out[idx] = cn;
    h_out[idx] = hn;
    if (h_out2) h_out2[idx] = hn;
}

// ---------------------------------------------------------------------------
extern "C" void kernel_launch(void* const* d_in, const int* in_sizes, int n_in,
                              void* d_out, int out_size)
{
    const float* kps   = (const float*)d_in[0];
    const float* h0    = (const float*)d_in[1];
    const float* h1    = (const float*)d_in[2];
    const float* h2    = (const float*)d_in[3];
    const float* c0    = (const float*)d_in[4];
    const float* c1    = (const float*)d_in[5];
    const float* c2    = (const float*)d_in[6];
    const float* W_emb = (const float*)d_in[7];
    const float* b_emb = (const float*)d_in[8];
    const float* w_ih1 = (const float*)d_in[9];
    const float* w_hh1 = (const float*)d_in[10];
    const float* b_ih1 = (const float*)d_in[11];
    const float* b_hh1 = (const float*)d_in[12];
    const float* w_ih2 = (const float*)d_in[13];
    const float* w_hh2 = (const float*)d_in[14];
    const float* b_ih2 = (const float*)d_in[15];
    const float* b_hh2 = (const float*)d_in[16];
    const float* w_ih3 = (const float*)d_in[17];
    const float* w_hh3 = (const float*)d_in[18];
    const float* b_ih3 = (const float*)d_in[19];
    const float* b_hh3 = (const float*)d_in[20];

    float* out = (float*)d_out;
    const size_t S = (size_t)BATCH * HID;
    // Output tuple: (h2n, h0n, h1n, h2n, c0n, c1n, c2n)
    float* out_h2n_a = out + 0 * S;
    float* out_h0n   = out + 1 * S;
    float* out_h1n   = out + 2 * S;
    float* out_h2n_b = out + 3 * S;
    float* out_c0n   = out + 4 * S;
    float* out_c1n   = out + 5 * S;
    float* out_c2n   = out + 6 * S;

    float* inframe = nullptr;
    float* gates   = nullptr;
    cudaGetSymbolAddress((void**)&inframe, g_inframe);
    cudaGetSymbolAddress((void**)&gates, g_gates);
    float* gates1 = gates + 0 * (size_t)BATCH * G4H;
    float* gates2 = gates + 1 * (size_t)BATCH * G4H;
    float* gates3 = gates + 2 * (size_t)BATCH * G4H;

    dim3 block(256);

    // 1) in_frame = kps @ W_emb^T + b_emb   [4096, 256]
    {
        dim3 grid(KPS / 128, BATCH / 128);
        gemm_dual_bias<128, 128, 16, 8, 8><<<grid, block>>>(
            kps, W_emb, KPS, nullptr, nullptr, 0, b_emb, nullptr, inframe, KPS);
    }

    // 2) gate GEMMs (all three independent given old h states)
    {
        dim3 grid(G4H / 128, BATCH / 128);
        // LSTM1: in_frame@w_ih1^T + h0@w_hh1^T
        gemm_dual_bias<128, 128, 16, 8, 8><<<grid, block>>>(
            inframe, w_ih1, KPS, h0, w_hh1, HID, b_ih1, b_hh1, gates1, G4H);
        // LSTM2: h0@w_ih2^T + h1@w_hh2^T  (OLD h0 per reference)
        gemm_dual_bias<128, 128, 16, 8, 8><<<grid, block>>>(
            h0, w_ih2, HID, h1, w_hh2, HID, b_ih2, b_hh2, gates2, G4H);
        // LSTM3: h1@w_ih3^T + h2@w_hh3^T  (OLD h1 per reference)
        gemm_dual_bias<128, 128, 16, 8, 8><<<grid, block>>>(
            h1, w_ih3, HID, h2, w_hh3, HID, b_ih3, b_hh3, gates3, G4H);
    }

    // 3) pointwise LSTM activations
    {
        int nblk = (BATCH * HID + 255) / 256;
        lstm_pointwise<<<nblk, 256>>>(gates1, c0, out_h0n, nullptr, out_c0n);
        lstm_pointwise<<<nblk, 256>>>(gates2, c1, out_h1n, nullptr, out_c1n);
        lstm_pointwise<<<nblk, 256>>>(gates3, c2, out_h2n_a, out_h2n_b, out_c2n);
    }
}

// round 3
// speedup vs baseline: 2.9476x; 2.9476x over previous
#include <cuda_runtime.h>
#include <cuda_bf16.h>
#include <stdint.h>
#include <math.h>

#define HID   1024
#define BATCH 4096
#define KPS   256
#define G4H   4096

#define BM 128
#define BN 128
#define BK 64
#define NS 3
#define A_BYTES     (BM * BK * 2)          // 16 KB
#define STAGE_BYTES (2 * A_BYTES)          // 32 KB
#define SMEM_SZ     (NS * STAGE_BYTES)     // 96 KB

// ===========================================================================
// Scratch (__device__ globals; sanctioned no-alloc mechanism)
// ===========================================================================
#define MEL (1024 * 1024)
__device__ __align__(128) __nv_bfloat16 g_bf[68 * MEL];   // 136 MB plane arena
__device__ float g_bias_perm[3 * G4H];

// arena offsets (elements)
#define O_X_HI    (0 * MEL)
#define O_X_LO    (1 * MEL)
#define O_H0_HI   (2 * MEL)
#define O_H0_LO   (6 * MEL)
#define O_H1_HI   (10 * MEL)
#define O_H1_LO   (14 * MEL)
#define O_H2_HI   (18 * MEL)
#define O_H2_LO   (22 * MEL)
#define O_WIH1_HI (26 * MEL)
#define O_WIH1_LO (27 * MEL)
#define O_WHH1_HI (28 * MEL)
#define O_WHH1_LO (32 * MEL)
#define O_WIH2_HI (36 * MEL)
#define O_WIH2_LO (40 * MEL)
#define O_WHH2_HI (44 * MEL)
#define O_WHH2_LO (48 * MEL)
#define O_WIH3_HI (52 * MEL)
#define O_WIH3_LO (56 * MEL)
#define O_WHH3_HI (60 * MEL)
#define O_WHH3_LO (64 * MEL)

// ===========================================================================
// Helpers
// ===========================================================================
__device__ __forceinline__ uint32_t smem_u32(const void* p) {
    uint32_t a;
    asm("{ .reg .u64 t; cvta.to.shared.u64 t, %1; cvt.u32.u64 %0, t; }" : "=r"(a) : "l"(p));
    return a;
}
__device__ __forceinline__ void cp_async16(uint32_t dst, const void* src) {
    asm volatile("cp.async.cg.shared.global [%0], [%1], 16;" :: "r"(dst), "l"(src));
}
__device__ __forceinline__ void ldsm_x4(uint32_t* r, uint32_t addr) {
    asm volatile("ldmatrix.sync.aligned.m8n8.x4.shared.b16 {%0,%1,%2,%3}, [%4];"
        : "=r"(r[0]), "=r"(r[1]), "=r"(r[2]), "=r"(r[3]) : "r"(addr));
}
__device__ __forceinline__ void mma16816(float* d, const uint32_t* a, uint32_t b0, uint32_t b1) {
    asm volatile("mma.sync.aligned.m16n8k16.row.col.f32.bf16.bf16.f32 "
        "{%0,%1,%2,%3}, {%4,%5,%6,%7}, {%8,%9}, {%0,%1,%2,%3};"
        : "+f"(d[0]), "+f"(d[1]), "+f"(d[2]), "+f"(d[3])
        : "r"(a[0]), "r"(a[1]), "r"(a[2]), "r"(a[3]), "r"(b0), "r"(b1));
}
__device__ __forceinline__ float sigmoidf_(float x) { return 1.0f / (1.0f + __expf(-x)); }

// ===========================================================================
// Conversion kernels
// ===========================================================================
__global__ void k_split(const float* __restrict__ src, __nv_bfloat16* __restrict__ hi,
                        __nv_bfloat16* __restrict__ lo, int n) {
    int i = blockIdx.x * blockDim.x + threadIdx.x;
    if (i >= n) return;
    float x = src[i];
    __nv_bfloat16 h = __float2bfloat16(x);
    hi[i] = h;
    lo[i] = __float2bfloat16(x - __bfloat162float(h));
}
// bias_perm[4j+g] = b_ih[g*HID+j] + b_hh[g*HID+j]
__global__ void k_bias_perm(const float* __restrict__ bih, const float* __restrict__ bhh,
                            float* __restrict__ out) {
    int n = blockIdx.x * blockDim.x + threadIdx.x;
    if (n >= G4H) return;
    int g = n & 3, j = n >> 2;
    out[n] = bih[g * HID + j] + bhh[g * HID + j];
}

// ===========================================================================
// Embedding SGEMM (fp32) with fused bf16 hi/lo split epilogue
//   C = kps @ W_emb^T + b_emb ; C -> (hi, lo) planes [4096, 256]
// ===========================================================================
__global__ void __launch_bounds__(256)
emb_gemm_split(const float* __restrict__ A1, const float* __restrict__ W1,
               const float* __restrict__ bias1,
               __nv_bfloat16* __restrict__ Chi, __nv_bfloat16* __restrict__ Clo)
{
    const int K1 = KPS, N = KPS;
    __shared__ float As[16][128];
    __shared__ float Bs[16][128];
    const int tid = threadIdx.x;
    const int m0 = blockIdx.y * 128;
    const int n0 = blockIdx.x * 128;
    const int ty = tid >> 4, tx = tid & 15;
    float acc[8][8];
#pragma unroll
    for (int i = 0; i < 8; i++)
#pragma unroll
        for (int j = 0; j < 8; j++) acc[i][j] = 0.0f;

    for (int k0 = 0; k0 < K1; k0 += 16) {
#pragma unroll
        for (int l = 0; l < 2; l++) {
            int f = tid + l * 256;
            int row = f / 4;
            int col4 = (f % 4) * 4;
            float4 v = *(const float4*)(A1 + (size_t)(m0 + row) * K1 + k0 + col4);
            As[col4 + 0][row] = v.x; As[col4 + 1][row] = v.y;
            As[col4 + 2][row] = v.z; As[col4 + 3][row] = v.w;
        }
#pragma unroll
        for (int l = 0; l < 2; l++) {
            int f = tid + l * 256;
            int row = f / 4;
            int col4 = (f % 4) * 4;
            float4 v = *(const float4*)(W1 + (size_t)(n0 + row) * K1 + k0 + col4);
            Bs[col4 + 0][row] = v.x; Bs[col4 + 1][row] = v.y;
            Bs[col4 + 2][row] = v.z; Bs[col4 + 3][row] = v.w;
        }
        __syncthreads();
#pragma unroll
        for (int k = 0; k < 16; k++) {
            float ar[8], br[8];
#pragma unroll
            for (int i = 0; i < 8; i++) ar[i] = As[k][ty * 8 + i];
#pragma unroll
            for (int j = 0; j < 8; j++) br[j] = Bs[k][tx * 8 + j];
#pragma unroll
            for (int i = 0; i < 8; i++)
#pragma unroll
                for (int j = 0; j < 8; j++)
                    acc[i][j] = fmaf(ar[i], br[j], acc[i][j]);
        }
        __syncthreads();
    }
#pragma unroll
    for (int i = 0; i < 8; i++) {
        int m = m0 + ty * 8 + i;
        int n = n0 + tx * 8;
#pragma unroll
        for (int j = 0; j < 8; j++) {
            float v = acc[i][j] + bias1[n + j];
            __nv_bfloat16 h = __float2bfloat16(v);
            Chi[(size_t)m * N + n + j] = h;
            Clo[(size_t)m * N + n + j] = __float2bfloat16(v - __bfloat162float(h));
        }
    }
}

// ===========================================================================
// Fused LSTM GEMM on mma.sync (HMMA): BM=128, BN=128(=32 j x 4 gates), BK=64
// 6 K-segments implement the bf16-split 3-product sum.
// ===========================================================================
struct SegInfo { const __nv_bfloat16 *A, *B; int K, ldA, ldB; };
struct LstmArgs {
    SegInfo seg[6];
    const float* bias;     // gate-interleaved [4096]: 4j+g
    const float* c_old;
    float* h_out; float* h_out2; float* c_out;
};
struct AllArgs { LstmArgs l[3]; };

__global__ void __launch_bounds__(256) lstm_gemm(AllArgs args)
{
    extern __shared__ __align__(1024) char smem[];
    const LstmArgs& L = args.l[blockIdx.z];
    const int m0   = blockIdx.y * BM;
    const int jb32 = blockIdx.x * 32;
    const int tid  = threadIdx.x;
    const int lane = tid & 31, wid = tid >> 5;
    const int warp_m = wid & 3, warp_n = wid >> 2;   // 4 x 2
    const int wm0 = warp_m * 32, wn0 = warp_n * 64;
    const uint32_t sb = smem_u32(smem);

    int cs[6];
    int a_ = 0;
#pragma unroll
    for (int i = 0; i < 6; i++) { a_ += (L.seg[i].K >> 6); cs[i] = a_; }
    const int KT = a_;

    float acc[16][4];
#pragma unroll
    for (int i = 0; i < 16; i++)
#pragma unroll
        for (int j = 0; j < 4; j++) acc[i][j] = 0.0f;

    auto load_stage = [&](int t) {
        const int s = t % NS;
        int seg = 0;
#pragma unroll
        for (int i = 0; i < 5; i++) if (t >= cs[i]) seg = i + 1;
        const int k0 = (t - (seg ? cs[seg - 1] : 0)) << 6;
        const __nv_bfloat16* Ap = L.seg[seg].A; const int ldA = L.seg[seg].ldA;
        const __nv_bfloat16* Bp = L.seg[seg].B; const int ldB = L.seg[seg].ldB;
        const uint32_t sa = sb + s * STAGE_BYTES;
        const uint32_t sB = sa + A_BYTES;
        // A: 128 rows x 8 chunks of 16B
#pragma unroll
        for (int i = 0; i < 4; i++) {
            int lin = tid + (i << 8);
            int r = lin >> 3, kc = lin & 7;
            cp_async16(sa + r * 128 + ((kc ^ (r & 7)) << 4),
                       Ap + (size_t)(m0 + r) * ldA + k0 + (kc << 3));
        }
        // B: gate-interleaved rows: smem n -> W row (n&3)*HID + jb32 + (n>>2)
#pragma unroll
        for (int i = 0; i < 4; i++) {
            int lin = tid + (i << 8);
            int n = lin >> 3, kc = lin & 7;
            int grow = (n & 3) * HID + jb32 + (n >> 2);
            cp_async16(sB + n * 128 + ((kc ^ (n & 7)) << 4),
                       Bp + (size_t)grow * ldB + k0 + (kc << 3));
        }
        asm volatile("cp.async.commit_group;" ::: "memory");
    };

    // prologue: NS-1 stages ahead
    for (int s = 0; s < NS - 1; s++) load_stage(s);

    for (int t = 0; t < KT; t++) {
        asm volatile("cp.async.wait_group %0;" :: "n"(NS - 2) : "memory");
        __syncthreads();
        const uint32_t sa = sb + (t % NS) * STAGE_BYTES;
        const uint32_t sB = sa + A_BYTES;
#pragma unroll
        for (int kk = 0; kk < 4; kk++) {
            uint32_t afr[2][4];
#pragma unroll
            for (int mt = 0; mt < 2; mt++) {
                int row = wm0 + mt * 16 + (lane & 15);
                int kc = kk * 2 + (lane >> 4);
                ldsm_x4(afr[mt], sa + row * 128 + ((kc ^ (row & 7)) << 4));
            }
#pragma unroll
            for (int op = 0; op < 4; op++) {
                uint32_t bfr[4];
                int n = wn0 + op * 16 + ((lane >> 4) << 3) + (lane & 7);
                int kc = kk * 2 + ((lane >> 3) & 1);
                ldsm_x4(bfr, sB + n * 128 + ((kc ^ (n & 7)) << 4));
#pragma unroll
                for (int mt = 0; mt < 2; mt++) {
                    mma16816(acc[mt * 8 + op * 2 + 0], afr[mt], bfr[0], bfr[1]);
                    mma16816(acc[mt * 8 + op * 2 + 1], afr[mt], bfr[2], bfr[3]);
                }
            }
        }
        if (t + NS - 1 < KT) load_stage(t + NS - 1);
    }

    // --------------------------------------------------------------
    // Fused LSTM epilogue. Columns are gate-interleaved: n -> (j = n>>2, g = n&3).
    // Each lane's fragment holds 2 adjacent cols x 2 rows; shfl.xor(1) pairs
    // (i,f) with (g,o) so each lane finishes one (row, j) completely.
    // --------------------------------------------------------------
    const float* __restrict__ bias = L.bias;
    const float* __restrict__ cold = L.c_old;
    const int qid = lane & 3;
#pragma unroll
    for (int mt = 0; mt < 2; mt++) {
#pragma unroll
        for (int oct = 0; oct < 8; oct++) {
            float c0 = acc[mt * 8 + oct][0], c1 = acc[mt * 8 + oct][1];
            float c2 = acc[mt * 8 + oct][2], c3 = acc[mt * 8 + oct][3];
            float o0 = __shfl_xor_sync(0xffffffffu, c0, 1);
            float o1 = __shfl_xor_sync(0xffffffffu, c1, 1);
            float o2 = __shfl_xor_sync(0xffffffffu, c2, 1);
            float o3 = __shfl_xor_sync(0xffffffffu, c3, 1);
            float gi, gf, gg, go;
            int r;
            if ((lane & 1) == 0) {      // even lane: owns (i,f), receives (g,o); does row+8
                gi = c2; gf = c3; gg = o2; go = o3;
                r = wm0 + mt * 16 + (lane >> 2) + 8;
            } else {                    // odd lane: owns (g,o), receives (i,f); does row
                gi = o0; gf = o1; gg = c0; go = c1;
                r = wm0 + mt * 16 + (lane >> 2);
            }
            const int j = jb32 + warp_n * 16 + oct * 2 + (qid >> 1);
            const float4 bb = *(const float4*)(bias + 4 * j);
            gi = sigmoidf_(gi + bb.x);
            gf = sigmoidf_(gf + bb.y);
            gg = tanhf(gg + bb.z);
            go = sigmoidf_(go + bb.w);
            const size_t idx = (size_t)(m0 + r) * HID + j;
            float cn = gf * cold[idx] + gi * gg;
            float hn = go * tanhf(cn);
            L.c_out[idx] = cn;
            L.h_out[idx] = hn;
            if (L.h_out2) L.h_out2[idx] = hn;
        }
    }
}

// ===========================================================================
extern "C" void kernel_launch(void* const* d_in, const int* in_sizes, int n_in,
                              void* d_out, int out_size)
{
    const float* kps   = (const float*)d_in[0];
    const float* h0    = (const float*)d_in[1];
    const float* h1    = (const float*)d_in[2];
    const float* h2    = (const float*)d_in[3];
    const float* c0    = (const float*)d_in[4];
    const float* c1    = (const float*)d_in[5];
    const float* c2    = (const float*)d_in[6];
    const float* W_emb = (const float*)d_in[7];
    const float* b_emb = (const float*)d_in[8];
    const float* w_ih1 = (const float*)d_in[9];
    const float* w_hh1 = (const float*)d_in[10];
    const float* b_ih1 = (const float*)d_in[11];
    const float* b_hh1 = (const float*)d_in[12];
    const float* w_ih2 = (const float*)d_in[13];
    const float* w_hh2 = (const float*)d_in[14];
    const float* b_ih2 = (const float*)d_in[15];
    const float* b_hh2 = (const float*)d_in[16];
    const float* w_ih3 = (const float*)d_in[17];
    const float* w_hh3 = (const float*)d_in[18];
    const float* b_ih3 = (const float*)d_in[19];
    const float* b_hh3 = (const float*)d_in[20];

    float* out = (float*)d_out;
    const size_t S = (size_t)BATCH * HID;
    float* out_h2n_a = out + 0 * S;
    float* out_h0n   = out + 1 * S;
    float* out_h1n   = out + 2 * S;
    float* out_h2n_b = out + 3 * S;
    float* out_c0n   = out + 4 * S;
    float* out_c1n   = out + 5 * S;
    float* out_c2n   = out + 6 * S;

    __nv_bfloat16* bf = nullptr;
    float* biasp = nullptr;
    cudaGetSymbolAddress((void**)&bf, g_bf);
    cudaGetSymbolAddress((void**)&biasp, g_bias_perm);

    const int T = 256;
    const int NH = BATCH * HID;          // 4M
    const int NW = G4H * HID;            // 4M (square weights)

    // --- plane conversions ---
    k_split<<<(NH + T - 1) / T, T>>>(h0, bf + O_H0_HI, bf + O_H0_LO, NH);
    k_split<<<(NH + T - 1) / T, T>>>(h1, bf + O_H1_HI, bf + O_H1_LO, NH);
    k_split<<<(NH + T - 1) / T, T>>>(h2, bf + O_H2_HI, bf + O_H2_LO, NH);
    k_split<<<(G4H * KPS + T - 1) / T, T>>>(w_ih1, bf + O_WIH1_HI, bf + O_WIH1_LO, G4H * KPS);
    k_split<<<(NW + T - 1) / T, T>>>(w_hh1, bf + O_WHH1_HI, bf + O_WHH1_LO, NW);
    k_split<<<(NW + T - 1) / T, T>>>(w_ih2, bf + O_WIH2_HI, bf + O_WIH2_LO, NW);
    k_split<<<(NW + T - 1) / T, T>>>(w_hh2, bf + O_WHH2_HI, bf + O_WHH2_LO, NW);
    k_split<<<(NW + T - 1) / T, T>>>(w_ih3, bf + O_WIH3_HI, bf + O_WIH3_LO, NW);
    k_split<<<(NW + T - 1) / T, T>>>(w_hh3, bf + O_WHH3_HI, bf + O_WHH3_LO, NW);
    k_bias_perm<<<G4H / T, T>>>(b_ih1, b_hh1, biasp + 0 * G4H);
    k_bias_perm<<<G4H / T, T>>>(b_ih2, b_hh2, biasp + 1 * G4H);
    k_bias_perm<<<G4H / T, T>>>(b_ih3, b_hh3, biasp + 2 * G4H);

    // --- embedding GEMM (fp32) with fused split ---
    emb_gemm_split<<<dim3(KPS / 128, BATCH / 128), 256>>>(
        kps, W_emb, b_emb, bf + O_X_HI, bf + O_X_LO);

    // --- fused LSTM GEMMs ---
    AllArgs A;
    {   // LSTM1: in_frame@wih1^T + h0@whh1^T
        LstmArgs& L = A.l[0];
        L.seg[0] = { bf + O_X_HI,  bf + O_WIH1_HI, KPS, KPS, KPS };
        L.seg[1] = { bf + O_X_LO,  bf + O_WIH1_HI, KPS, KPS, KPS };
        L.seg[2] = { bf + O_X_HI,  bf + O_WIH1_LO, KPS, KPS, KPS };
        L.seg[3] = { bf + O_H0_HI, bf + O_WHH1_HI, HID, HID, HID };
        L.seg[4] = { bf + O_H0_LO, bf + O_WHH1_HI, HID, HID, HID };
        L.seg[5] = { bf + O_H0_HI, bf + O_WHH1_LO, HID, HID, HID };
        L.bias = biasp + 0 * G4H; L.c_old = c0;
        L.h_out = out_h0n; L.h_out2 = nullptr; L.c_out = out_c0n;
    }
    {   // LSTM2: h0@wih2^T + h1@whh2^T (old h0 per reference)
        LstmArgs& L = A.l[1];
        L.seg[0] = { bf + O_H0_HI, bf + O_WIH2_HI, HID, HID, HID };
        L.seg[1] = { bf + O_H0_LO, bf + O_WIH2_HI, HID, HID, HID };
        L.seg[2] = { bf + O_H0_HI, bf + O_WIH2_LO, HID, HID, HID };
        L.seg[3] = { bf + O_H1_HI, bf + O_WHH2_HI, HID, HID, HID };
        L.seg[4] = { bf + O_H1_LO, bf + O_WHH2_HI, HID, HID, HID };
        L.seg[5] = { bf + O_H1_HI, bf + O_WHH2_LO, HID, HID, HID };
        L.bias = biasp + 1 * G4H; L.c_old = c1;
        L.h_out = out_h1n; L.h_out2 = nullptr; L.c_out = out_c1n;
    }
    {   // LSTM3: h1@wih3^T + h2@whh3^T (old h1 per reference)
        LstmArgs& L = A.l[2];
        L.seg[0] = { bf + O_H1_HI, bf + O_WIH3_HI, HID, HID, HID };
        L.seg[1] = { bf + O_H1_LO, bf + O_WIH3_HI, HID, HID, HID };
        L.seg[2] = { bf + O_H1_HI, bf + O_WIH3_LO, HID, HID, HID };
        L.seg[3] = { bf + O_H2_HI, bf + O_WHH3_HI, HID, HID, HID };
        L.seg[4] = { bf + O_H2_LO, bf + O_WHH3_HI, HID, HID, HID };
        L.seg[5] = { bf + O_H2_HI, bf + O_WHH3_LO, HID, HID, HID };
        L.bias = biasp + 2 * G4H; L.c_old = c2;
        L.h_out = out_h2n_a; L.h_out2 = out_h2n_b; L.c_out = out_c2n;
    }

    cudaFuncSetAttribute(lstm_gemm, cudaFuncAttributeMaxDynamicSharedMemorySize, SMEM_SZ);
    lstm_gemm<<<dim3(G4H / BN, BATCH / BM, 3), 256, SMEM_SZ>>>(A);
}

// round 4
// speedup vs baseline: 3.0835x; 1.0461x over previous
#include <cuda_runtime.h>
#include <cuda_bf16.h>
#include <stdint.h>
#include <math.h>

#define HID   1024
#define BATCH 4096
#define KPS   256
#define G4H   4096

#define BM 128
#define BN 128
#define BK 64
#define NS 3
#define A_BYTES     (BM * BK * 2)          // 16 KB
#define STAGE_BYTES (2 * A_BYTES)          // 32 KB
#define SMEM_SZ     (NS * STAGE_BYTES)     // 96 KB

// ===========================================================================
// Scratch (__device__ globals; sanctioned no-alloc mechanism)
// ===========================================================================
#define MEL (1024 * 1024)
__device__ __align__(128) __nv_bfloat16 g_bf[68 * MEL];   // 136 MB plane arena
__device__ float g_bias_perm[3 * G4H];

// arena offsets (elements)
#define O_X_HI    (0 * MEL)
#define O_X_LO    (1 * MEL)
#define O_H0_HI   (2 * MEL)
#define O_H0_LO   (6 * MEL)
#define O_H1_HI   (10 * MEL)
#define O_H1_LO   (14 * MEL)
#define O_H2_HI   (18 * MEL)
#define O_H2_LO   (22 * MEL)
#define O_WIH1_HI (26 * MEL)
#define O_WIH1_LO (27 * MEL)
#define O_WHH1_HI (28 * MEL)
#define O_WHH1_LO (32 * MEL)
#define O_WIH2_HI (36 * MEL)
#define O_WIH2_LO (40 * MEL)
#define O_WHH2_HI (44 * MEL)
#define O_WHH2_LO (48 * MEL)
#define O_WIH3_HI (52 * MEL)
#define O_WIH3_LO (56 * MEL)
#define O_WHH3_HI (60 * MEL)
#define O_WHH3_LO (64 * MEL)

// ===========================================================================
// Helpers
// ===========================================================================
__device__ __forceinline__ uint32_t smem_u32(const void* p) {
    uint32_t a;
    asm("{ .reg .u64 t; cvta.to.shared.u64 t, %1; cvt.u32.u64 %0, t; }" : "=r"(a) : "l"(p));
    return a;
}
__device__ __forceinline__ void cp_async16(uint32_t dst, const void* src) {
    asm volatile("cp.async.cg.shared.global [%0], [%1], 16;" :: "r"(dst), "l"(src));
}
__device__ __forceinline__ void ldsm_x4(uint32_t* r, uint32_t addr) {
    asm volatile("ldmatrix.sync.aligned.m8n8.x4.shared.b16 {%0,%1,%2,%3}, [%4];"
        : "=r"(r[0]), "=r"(r[1]), "=r"(r[2]), "=r"(r[3]) : "r"(addr));
}
__device__ __forceinline__ void mma16816(float* d, const uint32_t* a, uint32_t b0, uint32_t b1) {
    asm volatile("mma.sync.aligned.m16n8k16.row.col.f32.bf16.bf16.f32 "
        "{%0,%1,%2,%3}, {%4,%5,%6,%7}, {%8,%9}, {%0,%1,%2,%3};"
        : "+f"(d[0]), "+f"(d[1]), "+f"(d[2]), "+f"(d[3])
        : "r"(a[0]), "r"(a[1]), "r"(a[2]), "r"(a[3]), "r"(b0), "r"(b1));
}
__device__ __forceinline__ float sigmoidf_(float x) { return 1.0f / (1.0f + __expf(-x)); }

// ===========================================================================
// Vectorized split: float4 in, 2x bf16x2 out per plane. n must be /4.
// Grid-stride so a single launch can saturate HBM regardless of size.
// ===========================================================================
__global__ void k_split4(const float4* __restrict__ src,
                         __nv_bfloat162* __restrict__ hi,
                         __nv_bfloat162* __restrict__ lo, int n4) {
    int stride = gridDim.x * blockDim.x;
    for (int i = blockIdx.x * blockDim.x + threadIdx.x; i < n4; i += stride) {
        float4 v = src[i];
        __nv_bfloat162 h01 = __floats2bfloat162_rn(v.x, v.y);
        __nv_bfloat162 h23 = __floats2bfloat162_rn(v.z, v.w);
        float r0 = v.x - __bfloat162float(__low2bfloat16(h01));
        float r1 = v.y - __bfloat162float(__high2bfloat16(h01));
        float r2 = v.z - __bfloat162float(__low2bfloat16(h23));
        float r3 = v.w - __bfloat162float(__high2bfloat16(h23));
        hi[2 * i + 0] = h01;
        hi[2 * i + 1] = h23;
        lo[2 * i + 0] = __floats2bfloat162_rn(r0, r1);
        lo[2 * i + 1] = __floats2bfloat162_rn(r2, r3);
    }
}

// bias_perm[4j+g] = b_ih[g*HID+j] + b_hh[g*HID+j]
__global__ void k_bias_perm(const float* __restrict__ bih, const float* __restrict__ bhh,
                            float* __restrict__ out) {
    int n = blockIdx.x * blockDim.x + threadIdx.x;
    if (n >= G4H) return;
    int g = n & 3, j = n >> 2;
    out[n] = bih[g * HID + j] + bhh[g * HID + j];
}

// ===========================================================================
// Embedding SGEMM (fp32) with fused bf16 hi/lo split epilogue
// ===========================================================================
__global__ void __launch_bounds__(256)
emb_gemm_split(const float* __restrict__ A1, const float* __restrict__ W1,
               const float* __restrict__ bias1,
               __nv_bfloat16* __restrict__ Chi, __nv_bfloat16* __restrict__ Clo)
{
    const int K1 = KPS, N = KPS;
    __shared__ float As[16][128];
    __shared__ float Bs[16][128];
    const int tid = threadIdx.x;
    const int m0 = blockIdx.y * 128;
    const int n0 = blockIdx.x * 128;
    const int ty = tid >> 4, tx = tid & 15;
    float acc[8][8];
#pragma unroll
    for (int i = 0; i < 8; i++)
#pragma unroll
        for (int j = 0; j < 8; j++) acc[i][j] = 0.0f;

    for (int k0 = 0; k0 < K1; k0 += 16) {
#pragma unroll
        for (int l = 0; l < 2; l++) {
            int f = tid + l * 256;
            int row = f / 4;
            int col4 = (f % 4) * 4;
            float4 v = *(const float4*)(A1 + (size_t)(m0 + row) * K1 + k0 + col4);
            As[col4 + 0][row] = v.x; As[col4 + 1][row] = v.y;
            As[col4 + 2][row] = v.z; As[col4 + 3][row] = v.w;
        }
#pragma unroll
        for (int l = 0; l < 2; l++) {
            int f = tid + l * 256;
            int row = f / 4;
            int col4 = (f % 4) * 4;
            float4 v = *(const float4*)(W1 + (size_t)(n0 + row) * K1 + k0 + col4);
            Bs[col4 + 0][row] = v.x; Bs[col4 + 1][row] = v.y;
            Bs[col4 + 2][row] = v.z; Bs[col4 + 3][row] = v.w;
        }
        __syncthreads();
#pragma unroll
        for (int k = 0; k < 16; k++) {
            float ar[8], br[8];
#pragma unroll
            for (int i = 0; i < 8; i++) ar[i] = As[k][ty * 8 + i];
#pragma unroll
            for (int j = 0; j < 8; j++) br[j] = Bs[k][tx * 8 + j];
#pragma unroll
            for (int i = 0; i < 8; i++)
#pragma unroll
                for (int j = 0; j < 8; j++)
                    acc[i][j] = fmaf(ar[i], br[j], acc[i][j]);
        }
        __syncthreads();
    }
#pragma unroll
    for (int i = 0; i < 8; i++) {
        int m = m0 + ty * 8 + i;
        int n = n0 + tx * 8;
#pragma unroll
        for (int j = 0; j < 8; j++) {
            float v = acc[i][j] + bias1[n + j];
            __nv_bfloat16 h = __float2bfloat16(v);
            Chi[(size_t)m * N + n + j] = h;
            Clo[(size_t)m * N + n + j] = __float2bfloat16(v - __bfloat162float(h));
        }
    }
}

// ===========================================================================
// Fused LSTM GEMM on mma.sync (HMMA): BM=128, BN=128(=32 j x 4 gates), BK=64
// 6 K-segments implement the bf16-split 3-product sum.
// __launch_bounds__(256,2): cap regs at 128 so 2 CTAs/SM co-reside.
// ===========================================================================
struct SegInfo { const __nv_bfloat16 *A, *B; int K, ldA, ldB; };
struct LstmArgs {
    SegInfo seg[6];
    const float* bias;     // gate-interleaved [4096]: 4j+g
    const float* c_old;
    float* h_out; float* h_out2; float* c_out;
};
struct AllArgs { LstmArgs l[3]; };

__global__ void __launch_bounds__(256, 2) lstm_gemm(AllArgs args)
{
    extern __shared__ __align__(1024) char smem[];
    const LstmArgs& L = args.l[blockIdx.z];
    const int m0   = blockIdx.y * BM;
    const int jb32 = blockIdx.x * 32;
    const int tid  = threadIdx.x;
    const int lane = tid & 31, wid = tid >> 5;
    const int warp_m = wid & 3, warp_n = wid >> 2;   // 4 x 2
    const int wm0 = warp_m * 32, wn0 = warp_n * 64;
    const uint32_t sb = smem_u32(smem);

    int cs[6];
    int a_ = 0;
#pragma unroll
    for (int i = 0; i < 6; i++) { a_ += (L.seg[i].K >> 6); cs[i] = a_; }
    const int KT = a_;

    float acc[16][4];
#pragma unroll
    for (int i = 0; i < 16; i++)
#pragma unroll
        for (int j = 0; j < 4; j++) acc[i][j] = 0.0f;

    auto load_stage = [&](int t) {
        const int s = t % NS;
        int seg = 0;
#pragma unroll
        for (int i = 0; i < 5; i++) if (t >= cs[i]) seg = i + 1;
        const int k0 = (t - (seg ? cs[seg - 1] : 0)) << 6;
        const __nv_bfloat16* Ap = L.seg[seg].A; const int ldA = L.seg[seg].ldA;
        const __nv_bfloat16* Bp = L.seg[seg].B; const int ldB = L.seg[seg].ldB;
        const uint32_t sa = sb + s * STAGE_BYTES;
        const uint32_t sB = sa + A_BYTES;
        // A: 128 rows x 8 chunks of 16B
#pragma unroll
        for (int i = 0; i < 4; i++) {
            int lin = tid + (i << 8);
            int r = lin >> 3, kc = lin & 7;
            cp_async16(sa + r * 128 + ((kc ^ (r & 7)) << 4),
                       Ap + (size_t)(m0 + r) * ldA + k0 + (kc << 3));
        }
        // B: gate-interleaved rows: smem n -> W row (n&3)*HID + jb32 + (n>>2)
#pragma unroll
        for (int i = 0; i < 4; i++) {
            int lin = tid + (i << 8);
            int n = lin >> 3, kc = lin & 7;
            int grow = (n & 3) * HID + jb32 + (n >> 2);
            cp_async16(sB + n * 128 + ((kc ^ (n & 7)) << 4),
                       Bp + (size_t)grow * ldB + k0 + (kc << 3));
        }
        asm volatile("cp.async.commit_group;" ::: "memory");
    };

    // prologue: NS-1 stages ahead
    for (int s = 0; s < NS - 1; s++) load_stage(s);

    for (int t = 0; t < KT; t++) {
        asm volatile("cp.async.wait_group %0;" :: "n"(NS - 2) : "memory");
        __syncthreads();
        const uint32_t sa = sb + (t % NS) * STAGE_BYTES;
        const uint32_t sB = sa + A_BYTES;
#pragma unroll
        for (int kk = 0; kk < 4; kk++) {
            uint32_t afr[2][4];
#pragma unroll
            for (int mt = 0; mt < 2; mt++) {
                int row = wm0 + mt * 16 + (lane & 15);
                int kc = kk * 2 + (lane >> 4);
                ldsm_x4(afr[mt], sa + row * 128 + ((kc ^ (row & 7)) << 4));
            }
#pragma unroll
            for (int op = 0; op < 4; op++) {
                uint32_t bfr[4];
                int n = wn0 + op * 16 + ((lane >> 4) << 3) + (lane & 7);
                int kc = kk * 2 + ((lane >> 3) & 1);
                ldsm_x4(bfr, sB + n * 128 + ((kc ^ (n & 7)) << 4));
#pragma unroll
                for (int mt = 0; mt < 2; mt++) {
                    mma16816(acc[mt * 8 + op * 2 + 0], afr[mt], bfr[0], bfr[1]);
                    mma16816(acc[mt * 8 + op * 2 + 1], afr[mt], bfr[2], bfr[3]);
                }
            }
        }
        if (t + NS - 1 < KT) load_stage(t + NS - 1);
    }

    // --------------------------------------------------------------
    // Fused LSTM epilogue (gate-interleaved cols; shfl pairs (i,f)/(g,o)).
    // --------------------------------------------------------------
    const float* __restrict__ bias = L.bias;
    const float* __restrict__ cold = L.c_old;
    const int qid = lane & 3;
#pragma unroll
    for (int mt = 0; mt < 2; mt++) {
#pragma unroll
        for (int oct = 0; oct < 8; oct++) {
            float c0 = acc[mt * 8 + oct][0], c1 = acc[mt * 8 + oct][1];
            float c2 = acc[mt * 8 + oct][2], c3 = acc[mt * 8 + oct][3];
            float o0 = __shfl_xor_sync(0xffffffffu, c0, 1);
            float o1 = __shfl_xor_sync(0xffffffffu, c1, 1);
            float o2 = __shfl_xor_sync(0xffffffffu, c2, 1);
            float o3 = __shfl_xor_sync(0xffffffffu, c3, 1);
            float gi, gf, gg, go;
            int r;
            if ((lane & 1) == 0) {      // even lane: owns (i,f), receives (g,o); row+8
                gi = c2; gf = c3; gg = o2; go = o3;
                r = wm0 + mt * 16 + (lane >> 2) + 8;
            } else {                    // odd lane: owns (g,o), receives (i,f); row
                gi = o0; gf = o1; gg = c0; go = c1;
                r = wm0 + mt * 16 + (lane >> 2);
            }
            const int j = jb32 + warp_n * 16 + oct * 2 + (qid >> 1);
            const float4 bb = *(const float4*)(bias + 4 * j);
            gi = sigmoidf_(gi + bb.x);
            gf = sigmoidf_(gf + bb.y);
            gg = tanhf(gg + bb.z);
            go = sigmoidf_(go + bb.w);
            const size_t idx = (size_t)(m0 + r) * HID + j;
            float cn = gf * cold[idx] + gi * gg;
            float hn = go * tanhf(cn);
            L.c_out[idx] = cn;
            L.h_out[idx] = hn;
            if (L.h_out2) L.h_out2[idx] = hn;
        }
    }
}

// ===========================================================================
extern "C" void kernel_launch(void* const* d_in, const int* in_sizes, int n_in,
                              void* d_out, int out_size)
{
    const float* kps   = (const float*)d_in[0];
    const float* h0    = (const float*)d_in[1];
    const float* h1    = (const float*)d_in[2];
    const float* h2    = (const float*)d_in[3];
    const float* c0    = (const float*)d_in[4];
    const float* c1    = (const float*)d_in[5];
    const float* c2    = (const float*)d_in[6];
    const float* W_emb = (const float*)d_in[7];
    const float* b_emb = (const float*)d_in[8];
    const float* w_ih1 = (const float*)d_in[9];
    const float* w_hh1 = (const float*)d_in[10];
    const float* b_ih1 = (const float*)d_in[11];
    const float* b_hh1 = (const float*)d_in[12];
    const float* w_ih2 = (const float*)d_in[13];
    const float* w_hh2 = (const float*)d_in[14];
    const float* b_ih2 = (const float*)d_in[15];
    const float* b_hh2 = (const float*)d_in[16];
    const float* w_ih3 = (const float*)d_in[17];
    const float* w_hh3 = (const float*)d_in[18];
    const float* b_ih3 = (const float*)d_in[19];
    const float* b_hh3 = (const float*)d_in[20];

    float* out = (float*)d_out;
    const size_t S = (size_t)BATCH * HID;
    float* out_h2n_a = out + 0 * S;
    float* out_h0n   = out + 1 * S;
    float* out_h1n   = out + 2 * S;
    float* out_h2n_b = out + 3 * S;
    float* out_c0n   = out + 4 * S;
    float* out_c1n   = out + 5 * S;
    float* out_c2n   = out + 6 * S;

    __nv_bfloat16* bf = nullptr;
    float* biasp = nullptr;
    cudaGetSymbolAddress((void**)&bf, g_bf);
    cudaGetSymbolAddress((void**)&biasp, g_bias_perm);

    const int T = 256;
    const int NH4 = (BATCH * HID) / 4;   // 1M float4
    const int NW4 = (G4H * HID) / 4;     // 1M float4
    const int GB  = 1184;                // ~8 blocks/SM grid-stride

    // --- plane conversions (vectorized) ---
    k_split4<<<GB, T>>>((const float4*)h0, (__nv_bfloat162*)(bf + O_H0_HI),
                        (__nv_bfloat162*)(bf + O_H0_LO), NH4);
    k_split4<<<GB, T>>>((const float4*)h1, (__nv_bfloat162*)(bf + O_H1_HI),
                        (__nv_bfloat162*)(bf + O_H1_LO), NH4);
    k_split4<<<GB, T>>>((const float4*)h2, (__nv_bfloat162*)(bf + O_H2_HI),
                        (__nv_bfloat162*)(bf + O_H2_LO), NH4);
    k_split4<<<GB, T>>>((const float4*)w_ih1, (__nv_bfloat162*)(bf + O_WIH1_HI),
                        (__nv_bfloat162*)(bf + O_WIH1_LO), (G4H * KPS) / 4);
    k_split4<<<GB, T>>>((const float4*)w_hh1, (__nv_bfloat162*)(bf + O_WHH1_HI),
                        (__nv_bfloat162*)(bf + O_WHH1_LO), NW4);
    k_split4<<<GB, T>>>((const float4*)w_ih2, (__nv_bfloat162*)(bf + O_WIH2_HI),
                        (__nv_bfloat162*)(bf + O_WIH2_LO), NW4);
    k_split4<<<GB, T>>>((const float4*)w_hh2, (__nv_bfloat162*)(bf + O_WHH2_HI),
                        (__nv_bfloat162*)(bf + O_WHH2_LO), NW4);
    k_split4<<<GB, T>>>((const float4*)w_ih3, (__nv_bfloat162*)(bf + O_WIH3_HI),
                        (__nv_bfloat162*)(bf + O_WIH3_LO), NW4);
    k_split4<<<GB, T>>>((const float4*)w_hh3, (__nv_bfloat162*)(bf + O_WHH3_HI),
                        (__nv_bfloat162*)(bf + O_WHH3_LO), NW4);
    k_bias_perm<<<G4H / T, T>>>(b_ih1, b_hh1, biasp + 0 * G4H);
    k_bias_perm<<<G4H / T, T>>>(b_ih2, b_hh2, biasp + 1 * G4H);
    k_bias_perm<<<G4H / T, T>>>(b_ih3, b_hh3, biasp + 2 * G4H);

    // --- embedding GEMM (fp32) with fused split ---
    emb_gemm_split<<<dim3(KPS / 128, BATCH / 128), 256>>>(
        kps, W_emb, b_emb, bf + O_X_HI, bf + O_X_LO);

    // --- fused LSTM GEMMs ---
    AllArgs A;
    {   // LSTM1: in_frame@wih1^T + h0@whh1^T
        LstmArgs& L = A.l[0];
        L.seg[0] = { bf + O_X_HI,  bf + O_WIH1_HI, KPS, KPS, KPS };
        L.seg[1] = { bf + O_X_LO,  bf + O_WIH1_HI, KPS, KPS, KPS };
        L.seg[2] = { bf + O_X_HI,  bf + O_WIH1_LO, KPS, KPS, KPS };
        L.seg[3] = { bf + O_H0_HI, bf + O_WHH1_HI, HID, HID, HID };
        L.seg[4] = { bf + O_H0_LO, bf + O_WHH1_HI, HID, HID, HID };
        L.seg[5] = { bf + O_H0_HI, bf + O_WHH1_LO, HID, HID, HID };
        L.bias = biasp + 0 * G4H; L.c_old = c0;
        L.h_out = out_h0n; L.h_out2 = nullptr; L.c_out = out_c0n;
    }
    {   // LSTM2: h0@wih2^T + h1@whh2^T (old h0 per reference)
        LstmArgs& L = A.l[1];
        L.seg[0] = { bf + O_H0_HI, bf + O_WIH2_HI, HID, HID, HID };
        L.seg[1] = { bf + O_H0_LO, bf + O_WIH2_HI, HID, HID, HID };
        L.seg[2] = { bf + O_H0_HI, bf + O_WIH2_LO, HID, HID, HID };
        L.seg[3] = { bf + O_H1_HI, bf + O_WHH2_HI, HID, HID, HID };
        L.seg[4] = { bf + O_H1_LO, bf + O_WHH2_HI, HID, HID, HID };
        L.seg[5] = { bf + O_H1_HI, bf + O_WHH2_LO, HID, HID, HID };
        L.bias = biasp + 1 * G4H; L.c_old = c1;
        L.h_out = out_h1n; L.h_out2 = nullptr; L.c_out = out_c1n;
    }
    {   // LSTM3: h1@wih3^T + h2@whh3^T (old h1 per reference)
        LstmArgs& L = A.l[2];
        L.seg[0] = { bf + O_H1_HI, bf + O_WIH3_HI, HID, HID, HID };
        L.seg[1] = { bf + O_H1_LO, bf + O_WIH3_HI, HID, HID, HID };
        L.seg[2] = { bf + O_H1_HI, bf + O_WIH3_LO, HID, HID, HID };
        L.seg[3] = { bf + O_H2_HI, bf + O_WHH3_HI, HID, HID, HID };
        L.seg[4] = { bf + O_H2_LO, bf + O_WHH3_HI, HID, HID, HID };
        L.seg[5] = { bf + O_H2_HI, bf + O_WHH3_LO, HID, HID, HID };
        L.bias = biasp + 2 * G4H; L.c_old = c2;
        L.h_out = out_h2n_a; L.h_out2 = out_h2n_b; L.c_out = out_c2n;
    }

    cudaFuncSetAttribute(lstm_gemm, cudaFuncAttributeMaxDynamicSharedMemorySize, SMEM_SZ);
    lstm_gemm<<<dim3(G4H / BN, BATCH / BM, 3), 256, SMEM_SZ>>>(A);
}

// round 5
// speedup vs baseline: 4.2063x; 1.3641x over previous
#include <cuda_runtime.h>
#include <cuda_fp16.h>
#include <stdint.h>
#include <math.h>

#define HID   1024
#define BATCH 4096
#define KPS   256
#define G4H   4096

#define BM 128
#define BN 128
#define BK 64
#define NS 3
#define A_BYTES     (BM * BK * 2)          // 16 KB
#define STAGE_BYTES (2 * A_BYTES)          // 32 KB
#define SMEM_SZ     (NS * STAGE_BYTES)     // 96 KB

// ===========================================================================
// Scratch (__device__ globals; sanctioned no-alloc mechanism)
// ===========================================================================
#define MEL (1024 * 1024)
__device__ __align__(128) __half g_fp16[48 * MEL];   // 96 MB plane arena
__device__ float g_bias_perm[3 * G4H];

// arena offsets (half elements)
#define O_X_HI  (0 * MEL)
#define O_X_LO  (1 * MEL)
#define O_H0_HI (2 * MEL)
#define O_H0_LO (6 * MEL)
#define O_H1_HI (10 * MEL)
#define O_H1_LO (14 * MEL)
#define O_H2_HI (18 * MEL)
#define O_H2_LO (22 * MEL)
#define O_WIH1  (26 * MEL)
#define O_WHH1  (27 * MEL)
#define O_WIH2  (31 * MEL)
#define O_WHH2  (35 * MEL)
#define O_WIH3  (39 * MEL)
#define O_WHH3  (43 * MEL)

// ===========================================================================
// Helpers
// ===========================================================================
__device__ __forceinline__ uint32_t smem_u32(const void* p) {
    uint32_t a;
    asm("{ .reg .u64 t; cvta.to.shared.u64 t, %1; cvt.u32.u64 %0, t; }" : "=r"(a) : "l"(p));
    return a;
}
__device__ __forceinline__ void cp_async16(uint32_t dst, const void* src) {
    asm volatile("cp.async.cg.shared.global [%0], [%1], 16;" :: "r"(dst), "l"(src));
}
__device__ __forceinline__ void ldsm_x4(uint32_t* r, uint32_t addr) {
    asm volatile("ldmatrix.sync.aligned.m8n8.x4.shared.b16 {%0,%1,%2,%3}, [%4];"
        : "=r"(r[0]), "=r"(r[1]), "=r"(r[2]), "=r"(r[3]) : "r"(addr));
}
__device__ __forceinline__ void mma16816(float* d, const uint32_t* a, uint32_t b0, uint32_t b1) {
    asm volatile("mma.sync.aligned.m16n8k16.row.col.f32.f16.f16.f32 "
        "{%0,%1,%2,%3}, {%4,%5,%6,%7}, {%8,%9}, {%0,%1,%2,%3};"
        : "+f"(d[0]), "+f"(d[1]), "+f"(d[2]), "+f"(d[3])
        : "r"(a[0]), "r"(a[1]), "r"(a[2]), "r"(a[3]), "r"(b0), "r"(b1));
}
__device__ __forceinline__ float sigmoidf_(float x) { return 1.0f / (1.0f + __expf(-x)); }

// ===========================================================================
// Combined weight fp32->fp16 conversion: 6 jobs in one launch.
//   job0 = w_ih1 (256K float4), jobs 1..5 = square weights (1M float4 each)
// ===========================================================================
struct CvtJobs {
    const float4* src[6];
    __half2* dst[6];
    int n4[6];
};
#define WJ0_BLK 64
#define WJB_BLK 256
#define WCVT_GRID (WJ0_BLK + 5 * WJB_BLK)   // 1344

__global__ void k_cvt_w(CvtJobs J) {
    int bid = blockIdx.x;
    int job, lb, nb;
    if (bid < WJ0_BLK) { job = 0; lb = bid; nb = WJ0_BLK; }
    else { job = 1 + (bid - WJ0_BLK) / WJB_BLK; lb = (bid - WJ0_BLK) % WJB_BLK; nb = WJB_BLK; }
    const float4* __restrict__ src = J.src[job];
    __half2* __restrict__ dst = J.dst[job];
    const int n4 = J.n4[job];
    const int stride = nb * blockDim.x;
    for (int i = lb * blockDim.x + threadIdx.x; i < n4; i += stride) {
        float4 v = src[i];
        dst[2 * i + 0] = __floats2half2_rn(v.x, v.y);
        dst[2 * i + 1] = __floats2half2_rn(v.z, v.w);
    }
}

// ===========================================================================
// Combined h-state split: 3 jobs (h0,h1,h2), fp32 -> fp16 hi + fp16 lo
// ===========================================================================
struct SplitJobs {
    const float4* src[3];
    __half2* hi[3];
    __half2* lo[3];
};
#define SJ_BLK 384
#define SPLIT_GRID (3 * SJ_BLK)

__global__ void k_split_h(SplitJobs J) {
    const int job = blockIdx.x / SJ_BLK;
    const int lb  = blockIdx.x % SJ_BLK;
    const float4* __restrict__ src = J.src[job];
    __half2* __restrict__ hi = J.hi[job];
    __half2* __restrict__ lo = J.lo[job];
    const int n4 = (BATCH * HID) / 4;
    const int stride = SJ_BLK * blockDim.x;
    for (int i = lb * blockDim.x + threadIdx.x; i < n4; i += stride) {
        float4 v = src[i];
        __half2 h01 = __floats2half2_rn(v.x, v.y);
        __half2 h23 = __floats2half2_rn(v.z, v.w);
        float r0 = v.x - __half2float(__low2half(h01));
        float r1 = v.y - __half2float(__high2half(h01));
        float r2 = v.z - __half2float(__low2half(h23));
        float r3 = v.w - __half2float(__high2half(h23));
        hi[2 * i + 0] = h01;
        hi[2 * i + 1] = h23;
        lo[2 * i + 0] = __floats2half2_rn(r0, r1);
        lo[2 * i + 1] = __floats2half2_rn(r2, r3);
    }
}

// Combined bias perm: out[l][4j+g] = b_ih[l][g*HID+j] + b_hh[l][g*HID+j]
struct BiasJobs { const float* bih[3]; const float* bhh[3]; };
__global__ void k_bias_perm(BiasJobs J, float* __restrict__ out) {
    int idx = blockIdx.x * blockDim.x + threadIdx.x;   // 0..3*4096
    int l = idx >> 12, n = idx & 4095;
    int g = n & 3, j = n >> 2;
    out[idx] = J.bih[l][g * HID + j] + J.bhh[l][g * HID + j];
}

// ===========================================================================
// Embedding SGEMM (fp32) with fused fp16 hi/lo split epilogue
// ===========================================================================
__global__ void __launch_bounds__(256)
emb_gemm_split(const float* __restrict__ A1, const float* __restrict__ W1,
               const float* __restrict__ bias1,
               __half* __restrict__ Chi, __half* __restrict__ Clo)
{
    const int K1 = KPS, N = KPS;
    __shared__ float As[16][128];
    __shared__ float Bs[16][128];
    const int tid = threadIdx.x;
    const int m0 = blockIdx.y * 128;
    const int n0 = blockIdx.x * 128;
    const int ty = tid >> 4, tx = tid & 15;
    float acc[8][8];
#pragma unroll
    for (int i = 0; i < 8; i++)
#pragma unroll
        for (int j = 0; j < 8; j++) acc[i][j] = 0.0f;

    for (int k0 = 0; k0 < K1; k0 += 16) {
#pragma unroll
        for (int l = 0; l < 2; l++) {
            int f = tid + l * 256;
            int row = f / 4;
            int col4 = (f % 4) * 4;
            float4 v = *(const float4*)(A1 + (size_t)(m0 + row) * K1 + k0 + col4);
            As[col4 + 0][row] = v.x; As[col4 + 1][row] = v.y;
            As[col4 + 2][row] = v.z; As[col4 + 3][row] = v.w;
        }
#pragma unroll
        for (int l = 0; l < 2; l++) {
            int f = tid + l * 256;
            int row = f / 4;
            int col4 = (f % 4) * 4;
            float4 v = *(const float4*)(W1 + (size_t)(n0 + row) * K1 + k0 + col4);
            Bs[col4 + 0][row] = v.x; Bs[col4 + 1][row] = v.y;
            Bs[col4 + 2][row] = v.z; Bs[col4 + 3][row] = v.w;
        }
        __syncthreads();
#pragma unroll
        for (int k = 0; k < 16; k++) {
            float ar[8], br[8];
#pragma unroll
            for (int i = 0; i < 8; i++) ar[i] = As[k][ty * 8 + i];
#pragma unroll
            for (int j = 0; j < 8; j++) br[j] = Bs[k][tx * 8 + j];
#pragma unroll
            for (int i = 0; i < 8; i++)
#pragma unroll
                for (int j = 0; j < 8; j++)
                    acc[i][j] = fmaf(ar[i], br[j], acc[i][j]);
        }
        __syncthreads();
    }
#pragma unroll
    for (int i = 0; i < 8; i++) {
        int m = m0 + ty * 8 + i;
        int n = n0 + tx * 8;
#pragma unroll
        for (int j = 0; j < 8; j++) {
            float v = acc[i][j] + bias1[n + j];
            __half h = __float2half_rn(v);
            Chi[(size_t)m * N + n + j] = h;
            Clo[(size_t)m * N + n + j] = __float2half_rn(v - __half2float(h));
        }
    }
}

// ===========================================================================
// Fused LSTM GEMM on mma.sync (HMMA fp16): BM=128, BN=128 (32 j x 4 gates), BK=64
// 4 K-segments implement the fp16 2-product split: hiA@W + loA@W per input.
// ===========================================================================
struct SegInfo { const __half *A, *B; int K, ldA, ldB; };
struct LstmArgs {
    SegInfo seg[4];
    const float* bias;     // gate-interleaved [4096]: 4j+g
    const float* c_old;
    float* h_out; float* h_out2; float* c_out;
};
struct AllArgs { LstmArgs l[3]; };

__global__ void __launch_bounds__(256) lstm_gemm(AllArgs args)
{
    extern __shared__ __align__(1024) char smem[];
    const LstmArgs& L = args.l[blockIdx.z];
    const int m0   = blockIdx.y * BM;
    const int jb32 = blockIdx.x * 32;
    const int tid  = threadIdx.x;
    const int lane = tid & 31, wid = tid >> 5;
    const int warp_m = wid & 3, warp_n = wid >> 2;   // 4 x 2
    const int wm0 = warp_m * 32, wn0 = warp_n * 64;
    const uint32_t sb = smem_u32(smem);

    int cs[4];
    int a_ = 0;
#pragma unroll
    for (int i = 0; i < 4; i++) { a_ += (L.seg[i].K >> 6); cs[i] = a_; }
    const int KT = a_;

    float acc[16][4];
#pragma unroll
    for (int i = 0; i < 16; i++)
#pragma unroll
        for (int j = 0; j < 4; j++) acc[i][j] = 0.0f;

    auto load_stage = [&](int t) {
        const int s = t % NS;
        int seg = 0;
#pragma unroll
        for (int i = 0; i < 3; i++) if (t >= cs[i]) seg = i + 1;
        const int k0 = (t - (seg ? cs[seg - 1] : 0)) << 6;
        const __half* Ap = L.seg[seg].A; const int ldA = L.seg[seg].ldA;
        const __half* Bp = L.seg[seg].B; const int ldB = L.seg[seg].ldB;
        const uint32_t sa = sb + s * STAGE_BYTES;
        const uint32_t sB = sa + A_BYTES;
        // A: 128 rows x 8 chunks of 16B
#pragma unroll
        for (int i = 0; i < 4; i++) {
            int lin = tid + (i << 8);
            int r = lin >> 3, kc = lin & 7;
            cp_async16(sa + r * 128 + ((kc ^ (r & 7)) << 4),
                       Ap + (size_t)(m0 + r) * ldA + k0 + (kc << 3));
        }
        // B: gate-interleaved rows: smem n -> W row (n&3)*HID + jb32 + (n>>2)
#pragma unroll
        for (int i = 0; i < 4; i++) {
            int lin = tid + (i << 8);
            int n = lin >> 3, kc = lin & 7;
            int grow = (n & 3) * HID + jb32 + (n >> 2);
            cp_async16(sB + n * 128 + ((kc ^ (n & 7)) << 4),
                       Bp + (size_t)grow * ldB + k0 + (kc << 3));
        }
        asm volatile("cp.async.commit_group;" ::: "memory");
    };

    // prologue: NS-1 stages ahead
    for (int s = 0; s < NS - 1; s++) load_stage(s);

    for (int t = 0; t < KT; t++) {
        asm volatile("cp.async.wait_group %0;" :: "n"(NS - 2) : "memory");
        __syncthreads();
        const uint32_t sa = sb + (t % NS) * STAGE_BYTES;
        const uint32_t sB = sa + A_BYTES;
#pragma unroll
        for (int kk = 0; kk < 4; kk++) {
            uint32_t afr[2][4];
#pragma unroll
            for (int mt = 0; mt < 2; mt++) {
                int row = wm0 + mt * 16 + (lane & 15);
                int kc = kk * 2 + (lane >> 4);
                ldsm_x4(afr[mt], sa + row * 128 + ((kc ^ (row & 7)) << 4));
            }
#pragma unroll
            for (int op = 0; op < 4; op++) {
                uint32_t bfr[4];
                int n = wn0 + op * 16 + ((lane >> 4) << 3) + (lane & 7);
                int kc = kk * 2 + ((lane >> 3) & 1);
                ldsm_x4(bfr, sB + n * 128 + ((kc ^ (n & 7)) << 4));
#pragma unroll
                for (int mt = 0; mt < 2; mt++) {
                    mma16816(acc[mt * 8 + op * 2 + 0], afr[mt], bfr[0], bfr[1]);
                    mma16816(acc[mt * 8 + op * 2 + 1], afr[mt], bfr[2], bfr[3]);
                }
            }
        }
        if (t + NS - 1 < KT) load_stage(t + NS - 1);
    }

    // --------------------------------------------------------------
    // Fused LSTM epilogue (gate-interleaved cols; shfl pairs (i,f)/(g,o)).
    // --------------------------------------------------------------
    const float* __restrict__ bias = L.bias;
    const float* __restrict__ cold = L.c_old;
    const int qid = lane & 3;
#pragma unroll
    for (int mt = 0; mt < 2; mt++) {
#pragma unroll
        for (int oct = 0; oct < 8; oct++) {
            float c0 = acc[mt * 8 + oct][0], c1 = acc[mt * 8 + oct][1];
            float c2 = acc[mt * 8 + oct][2], c3 = acc[mt * 8 + oct][3];
            float o0 = __shfl_xor_sync(0xffffffffu, c0, 1);
            float o1 = __shfl_xor_sync(0xffffffffu, c1, 1);
            float o2 = __shfl_xor_sync(0xffffffffu, c2, 1);
            float o3 = __shfl_xor_sync(0xffffffffu, c3, 1);
            float gi, gf, gg, go;
            int r;
            if ((lane & 1) == 0) {      // even lane: owns (i,f), receives (g,o); row+8
                gi = c2; gf = c3; gg = o2; go = o3;
                r = wm0 + mt * 16 + (lane >> 2) + 8;
            } else {                    // odd lane: owns (g,o), receives (i,f); row
                gi = o0; gf = o1; gg = c0; go = c1;
                r = wm0 + mt * 16 + (lane >> 2);
            }
            const int j = jb32 + warp_n * 16 + oct * 2 + (qid >> 1);
            const float4 bb = *(const float4*)(bias + 4 * j);
            gi = sigmoidf_(gi + bb.x);
            gf = sigmoidf_(gf + bb.y);
            gg = tanhf(gg + bb.z);
            go = sigmoidf_(go + bb.w);
            const size_t idx = (size_t)(m0 + r) * HID + j;
            float cn = gf * cold[idx] + gi * gg;
            float hn = go * tanhf(cn);
            L.c_out[idx] = cn;
            L.h_out[idx] = hn;
            if (L.h_out2) L.h_out2[idx] = hn;
        }
    }
}

// ===========================================================================
extern "C" void kernel_launch(void* const* d_in, const int* in_sizes, int n_in,
                              void* d_out, int out_size)
{
    const float* kps   = (const float*)d_in[0];
    const float* h0    = (const float*)d_in[1];
    const float* h1    = (const float*)d_in[2];
    const float* h2    = (const float*)d_in[3];
    const float* c0    = (const float*)d_in[4];
    const float* c1    = (const float*)d_in[5];
    const float* c2    = (const float*)d_in[6];
    const float* W_emb = (const float*)d_in[7];
    const float* b_emb = (const float*)d_in[8];
    const float* w_ih1 = (const float*)d_in[9];
    const float* w_hh1 = (const float*)d_in[10];
    const float* b_ih1 = (const float*)d_in[11];
    const float* b_hh1 = (const float*)d_in[12];
    const float* w_ih2 = (const float*)d_in[13];
    const float* w_hh2 = (const float*)d_in[14];
    const float* b_ih2 = (const float*)d_in[15];
    const float* b_hh2 = (const float*)d_in[16];
    const float* w_ih3 = (const float*)d_in[17];
    const float* w_hh3 = (const float*)d_in[18];
    const float* b_ih3 = (const float*)d_in[19];
    const float* b_hh3 = (const float*)d_in[20];

    float* out = (float*)d_out;
    const size_t S = (size_t)BATCH * HID;
    float* out_h2n_a = out + 0 * S;
    float* out_h0n   = out + 1 * S;
    float* out_h1n   = out + 2 * S;
    float* out_h2n_b = out + 3 * S;
    float* out_c0n   = out + 4 * S;
    float* out_c1n   = out + 5 * S;
    float* out_c2n   = out + 6 * S;

    __half* hp = nullptr;
    float* biasp = nullptr;
    cudaGetSymbolAddress((void**)&hp, g_fp16);
    cudaGetSymbolAddress((void**)&biasp, g_bias_perm);

    // --- weight conversions (one launch, 6 jobs) ---
    CvtJobs W;
    W.src[0] = (const float4*)w_ih1; W.dst[0] = (__half2*)(hp + O_WIH1); W.n4[0] = (G4H * KPS) / 4;
    W.src[1] = (const float4*)w_hh1; W.dst[1] = (__half2*)(hp + O_WHH1); W.n4[1] = (G4H * HID) / 4;
    W.src[2] = (const float4*)w_ih2; W.dst[2] = (__half2*)(hp + O_WIH2); W.n4[2] = (G4H * HID) / 4;
    W.src[3] = (const float4*)w_hh2; W.dst[3] = (__half2*)(hp + O_WHH2); W.n4[3] = (G4H * HID) / 4;
    W.src[4] = (const float4*)w_ih3; W.dst[4] = (__half2*)(hp + O_WIH3); W.n4[4] = (G4H * HID) / 4;
    W.src[5] = (const float4*)w_hh3; W.dst[5] = (__half2*)(hp + O_WHH3); W.n4[5] = (G4H * HID) / 4;
    k_cvt_w<<<WCVT_GRID, 256>>>(W);

    // --- h-state splits (one launch, 3 jobs) ---
    SplitJobs H;
    H.src[0] = (const float4*)h0; H.hi[0] = (__half2*)(hp + O_H0_HI); H.lo[0] = (__half2*)(hp + O_H0_LO);
    H.src[1] = (const float4*)h1; H.hi[1] = (__half2*)(hp + O_H1_HI); H.lo[1] = (__half2*)(hp + O_H1_LO);
    H.src[2] = (const float4*)h2; H.hi[2] = (__half2*)(hp + O_H2_HI); H.lo[2] = (__half2*)(hp + O_H2_LO);
    k_split_h<<<SPLIT_GRID, 256>>>(H);

    // --- bias perms (one launch, 3 jobs) ---
    BiasJobs BJ;
    BJ.bih[0] = b_ih1; BJ.bhh[0] = b_hh1;
    BJ.bih[1] = b_ih2; BJ.bhh[1] = b_hh2;
    BJ.bih[2] = b_ih3; BJ.bhh[2] = b_hh3;
    k_bias_perm<<<(3 * G4H) / 256, 256>>>(BJ, biasp);

    // --- embedding GEMM (fp32) with fused fp16 split ---
    emb_gemm_split<<<dim3(KPS / 128, BATCH / 128), 256>>>(
        kps, W_emb, b_emb, hp + O_X_HI, hp + O_X_LO);

    // --- fused LSTM GEMMs (fp16 2-product) ---
    AllArgs A;
    {   // LSTM1: (x_hi + x_lo)@wih1^T + (h0_hi + h0_lo)@whh1^T
        LstmArgs& L = A.l[0];
        L.seg[0] = { hp + O_X_HI,  hp + O_WIH1, KPS, KPS, KPS };
        L.seg[1] = { hp + O_X_LO,  hp + O_WIH1, KPS, KPS, KPS };
        L.seg[2] = { hp + O_H0_HI, hp + O_WHH1, HID, HID, HID };
        L.seg[3] = { hp + O_H0_LO, hp + O_WHH1, HID, HID, HID };
        L.bias = biasp + 0 * G4H; L.c_old = c0;
        L.h_out = out_h0n; L.h_out2 = nullptr; L.c_out = out_c0n;
    }
    {   // LSTM2: h0@wih2^T + h1@whh2^T (old h0 per reference)
        LstmArgs& L = A.l[1];
        L.seg[0] = { hp + O_H0_HI, hp + O_WIH2, HID, HID, HID };
        L.seg[1] = { hp + O_H0_LO, hp + O_WIH2, HID, HID, HID };
        L.seg[2] = { hp + O_H1_HI, hp + O_WHH2, HID, HID, HID };
        L.seg[3] = { hp + O_H1_LO, hp + O_WHH2, HID, HID, HID };
        L.bias = biasp + 1 * G4H; L.c_old = c1;
        L.h_out = out_h1n; L.h_out2 = nullptr; L.c_out = out_c1n;
    }
    {   // LSTM3: h1@wih3^T + h2@whh3^T (old h1 per reference)
        LstmArgs& L = A.l[2];
        L.seg[0] = { hp + O_H1_HI, hp + O_WIH3, HID, HID, HID };
        L.seg[1] = { hp + O_H1_LO, hp + O_WIH3, HID, HID, HID };
        L.seg[2] = { hp + O_H2_HI, hp + O_WHH3, HID, HID, HID };
        L.seg[3] = { hp + O_H2_LO, hp + O_WHH3, HID, HID, HID };
        L.bias = biasp + 2 * G4H; L.c_old = c2;
        L.h_out = out_h2n_a; L.h_out2 = out_h2n_b; L.c_out = out_c2n;
    }

    cudaFuncSetAttribute(lstm_gemm, cudaFuncAttributeMaxDynamicSharedMemorySize, SMEM_SZ);
    lstm_gemm<<<dim3(G4H / BN, BATCH / BM, 3), 256, SMEM_SZ>>>(A);
}